// round 17
// baseline (speedup 1.0000x reference)
#include <cuda_runtime.h>
#include <cuda_fp16.h>
#include <math.h>
#include <stdint.h>

// Problem constants
#define BB 2
#define SS 2048
#define DD 1024
#define HH 16
#define HDIM 64
#define II 3752
#define MROWS (BB*SS)          // 4096
#define EPS 1e-6f
#define FULLMASK 0xffffffffu
#define LDQKV (3*DD)           // 3072

// ---------------- scratch (device globals) ----------------
__device__ __align__(16) __half g_h   [MROWS * DD];
__device__ __align__(16) __half g_qkv [MROWS * LDQKV];
__device__ __align__(16) __half g_att [MROWS * DD];
__device__ float  g_res1[MROWS * DD];
__device__ __align__(16) __half g_h2  [MROWS * DD];
__device__ __align__(16) __half g_sgate[MROWS * II];   // silu(gate), fp16
__device__ __align__(16) __half g_act [MROWS * II];
__device__ __align__(16) __half g_cw  [4 * DD * DD + 3 * DD * II];
__device__ float  g_bcat[LDQKV];

#define CW_QKV 0
#define CW_O  (3*DD*DD)
#define CW_G  (4*DD*DD)
#define CW_U  (4*DD*DD + DD*II)
#define CW_D  (4*DD*DD + 2*DD*II)

// ---------------- helpers ----------------
__device__ __forceinline__ void mma_f16(float* d, const uint32_t* a, const uint32_t* b) {
    asm("mma.sync.aligned.m16n8k16.row.col.f32.f16.f16.f32 "
        "{%0,%1,%2,%3},{%4,%5,%6,%7},{%8,%9},{%0,%1,%2,%3};"
        : "+f"(d[0]), "+f"(d[1]), "+f"(d[2]), "+f"(d[3])
        : "r"(a[0]), "r"(a[1]), "r"(a[2]), "r"(a[3]), "r"(b[0]), "r"(b[1]));
}

#define LDSM_X4(r, addr) \
    asm volatile("ldmatrix.sync.aligned.m8n8.x4.shared.b16 {%0,%1,%2,%3}, [%4];" \
        : "=r"((r)[0]), "=r"((r)[1]), "=r"((r)[2]), "=r"((r)[3]) : "r"(addr))
#define LDSM_X2(r, addr) \
    asm volatile("ldmatrix.sync.aligned.m8n8.x2.shared.b16 {%0,%1}, [%2];" \
        : "=r"((r)[0]), "=r"((r)[1]) : "r"(addr))
#define LDSM_X2T(r, addr) \
    asm volatile("ldmatrix.sync.aligned.m8n8.x2.trans.shared.b16 {%0,%1}, [%2];" \
        : "=r"((r)[0]), "=r"((r)[1]) : "r"(addr))
#define LDSM_X4T(r, addr) \
    asm volatile("ldmatrix.sync.aligned.m8n8.x4.trans.shared.b16 {%0,%1,%2,%3}, [%4];" \
        : "=r"((r)[0]), "=r"((r)[1]), "=r"((r)[2]), "=r"((r)[3]) : "r"(addr))

#define CP_ASYNC(dst, src, sz) \
    asm volatile("cp.async.cg.shared.global [%0], [%1], 16, %2;\n" :: "r"(dst), "l"(src), "r"(sz))
#define CP_COMMIT asm volatile("cp.async.commit_group;\n" ::)
#define CP_WAIT1  asm volatile("cp.async.wait_group 1;\n" ::)

// ---------------- weight converts (RN-round to fp16 once per replay) --------
__global__ void cvt_all_kernel(const float* __restrict__ wo, const float* __restrict__ wg,
                               const float* __restrict__ wu, const float* __restrict__ wd,
                               __half* __restrict__ cw)
{
    const int N_O = DD * DD / 4;
    const int N_I = DD * II / 4;
    int i = blockIdx.x * 256 + threadIdx.x;
    const float* src; __half* dst; int j;
    if (i < N_O)                  { src = wo; dst = cw + CW_O; j = i; }
    else if (i < N_O + N_I)       { src = wg; dst = cw + CW_G; j = i - N_O; }
    else if (i < N_O + 2 * N_I)   { src = wu; dst = cw + CW_U; j = i - N_O - N_I; }
    else if (i < N_O + 3 * N_I)   { src = wd; dst = cw + CW_D; j = i - N_O - 2 * N_I; }
    else return;
    float4 v = ((const float4*)src)[j];
    __half2* d2 = (__half2*)(dst + (size_t)j * 4);
    d2[0] = __floats2half2_rn(v.x, v.y);
    d2[1] = __floats2half2_rn(v.z, v.w);
}

__global__ void cvt_qkv_kernel(const float* __restrict__ wq, const float* __restrict__ wk,
                               const float* __restrict__ wv, __half* __restrict__ dst)
{
    const int PER = DD * DD / 4;
    int i = blockIdx.x * 256 + threadIdx.x;
    int which = i / PER;
    int j = i - which * PER;
    const float* src = (which == 0) ? wq : (which == 1) ? wk : wv;
    float4 v = ((const float4*)src)[j];
    int k = j >> 8;
    int n4 = j & 255;
    __half2* d2 = (__half2*)(dst + (size_t)k * LDQKV + which * DD + n4 * 4);
    d2[0] = __floats2half2_rn(v.x, v.y);
    d2[1] = __floats2half2_rn(v.z, v.w);
}

__global__ void bcat_kernel(const float* __restrict__ bq, const float* __restrict__ bk,
                            const float* __restrict__ bv, float* __restrict__ dst)
{
    int i = blockIdx.x * 256 + threadIdx.x;
    if (i < LDQKV) {
        int which = i >> 10, j = i & 1023;
        dst[i] = (which == 0) ? bq[j] : (which == 1) ? bk[j] : bv[j];
    }
}

// ---------------- RMSNorm (single pass, output fp16) ----------------
__global__ void rmsnorm_kernel(const float* __restrict__ x, const float* __restrict__ w,
                               __half* __restrict__ out)
{
    int row = blockIdx.x;
    int tid = threadIdx.x;
    float4 v = ((const float4*)(x + (size_t)row * DD))[tid];
    float sum = v.x * v.x + v.y * v.y + v.z * v.z + v.w * v.w;

    __shared__ float red[256];
    #pragma unroll
    for (int s = 16; s > 0; s >>= 1) sum += __shfl_xor_sync(FULLMASK, sum, s);
    if ((tid & 31) == 0) red[tid >> 5] = sum;
    __syncthreads();
    if (tid < 8) {
        float t = red[tid];
        #pragma unroll
        for (int s = 4; s > 0; s >>= 1) t += __shfl_xor_sync(0xFF, t, s);
        if (tid == 0) red[0] = t;
    }
    __syncthreads();
    float r = rsqrtf(red[0] * (1.0f / DD) + EPS);

    float4 wv = ((const float4*)w)[tid];
    __half2* o2 = (__half2*)(out + (size_t)row * DD + tid * 4);
    o2[0] = __floats2half2_rn(wv.x * (v.x * r), wv.y * (v.y * r));
    o2[1] = __floats2half2_rn(wv.z * (v.z * r), wv.w * (v.w * r));
}

// ---------------- pipelined fp16 GEMM: 128x128 block, warp 64x32, GBK=64, 3-stage ----
#define GBM 128
#define GBN 128
#define GBK 64          // halves per k-tile
#define NSTG 3
#define ASTRIDEH 72     // 64 + 8 pad
#define BSTRIDEH 136    // 128 + 8 pad
#define ASZH (GBM*ASTRIDEH)     // 9216
#define BSZH (GBK*BSTRIDEH)     // 8704
#define STGH (ASZH+BSZH)        // 17920 halves = 35840 B
#define GEMM_SMEM_BYTES (NSTG*STGH*2)   // 107520

__device__ __forceinline__ void gemm_load_stage(
    const __half* __restrict__ A, const __half* __restrict__ W,
    int N, int K, int bm, int bn, int k0, uint32_t su, int tid)
{
    // A: 128 rows x 64 halves = 1024 x 16B chunks -> 4 per thread
    #pragma unroll
    for (int u = 0; u < 4; u++) {
        int id = tid + u * 256;
        int row = id >> 3, ch = id & 7;
        int kk = k0 + ch * 8;
        int sz = (kk + 8 <= K) ? 16 : 0;
        const __half* src = A + (size_t)(bm + row) * K + (sz ? kk : 0);
        uint32_t dst = su + (row * ASTRIDEH + ch * 8) * 2;
        CP_ASYNC(dst, src, sz);
    }
    // B: 64 rows x 128 halves = 1024 x 16B chunks -> 4 per thread
    #pragma unroll
    for (int u = 0; u < 4; u++) {
        int id = tid + u * 256;
        int row = id >> 4, ch = id & 15;
        int kk = k0 + row, col = bn + ch * 8;
        int sz = (kk < K && col + 8 <= N) ? 16 : 0;
        const __half* src = W + (sz ? ((size_t)kk * N + col) : 0);
        uint32_t dst = su + (ASZH + row * BSTRIDEH + ch * 8) * 2;
        CP_ASYNC(dst, src, sz);
    }
}

// outmode: 0 = f32, 2 = f16, 3 = silu -> f16
__global__ __launch_bounds__(256) void gemm_f16_kernel(
    const __half* __restrict__ A, const __half* __restrict__ W,
    const float* __restrict__ bias, const float* __restrict__ res,
    const __half* __restrict__ gate, void* __restrict__ C,
    int M, int N, int K, int outmode)
{
    extern __shared__ __half smemh[];
    const uint32_t sbase = (uint32_t)__cvta_generic_to_shared(smemh);

    const int tid  = threadIdx.x;
    const int lane = tid & 31;
    const int warp = tid >> 5;
    const int wm = warp >> 2;
    const int wn = warp & 3;
    const int grp = lane >> 2;
    const int tig = lane & 3;

    const int bm = blockIdx.y * GBM;
    const int bn = blockIdx.x * GBN;

    float acc[4][4][4];
    #pragma unroll
    for (int i = 0; i < 4; i++)
        #pragma unroll
        for (int j = 0; j < 4; j++)
            #pragma unroll
            for (int r = 0; r < 4; r++) acc[i][j][r] = 0.f;

    const int T = (K + GBK - 1) / GBK;

    #pragma unroll
    for (int s = 0; s < 2; s++) {
        gemm_load_stage(A, W, N, K, bm, bn, s * GBK, sbase + s * STGH * 2, tid);
        CP_COMMIT;
    }

    const int a_row  = (lane & 15);
    const int a_koff = (lane >> 4) * 8;
    // B x4.trans lane mapping: m = lane>>3; row = (m&1)*8 + (lane&7); coloff = (m>>1)*8
    const int b_m    = lane >> 3;
    const int b_rowo = (b_m & 1) * 8 + (lane & 7);
    const int b_colo = (b_m >> 1) * 8;

    for (int t = 0; t < T; t++) {
        CP_WAIT1;
        __syncthreads();

        uint32_t su = sbase + (t % NSTG) * STGH * 2;
        uint32_t sa = su;
        uint32_t sb = su + ASZH * 2;

        #pragma unroll
        for (int ks = 0; ks < 4; ks++) {
            uint32_t af[4][4];
            #pragma unroll
            for (int mt = 0; mt < 4; mt++) {
                int row = wm * 64 + mt * 16 + a_row;
                LDSM_X4(af[mt], sa + (row * ASTRIDEH + ks * 16 + a_koff) * 2);
            }
            uint32_t bf[2][4];   // bf[p] covers nt = 2p (regs 0,1) and 2p+1 (regs 2,3)
            #pragma unroll
            for (int p = 0; p < 2; p++) {
                int krow = ks * 16 + b_rowo;
                int col  = wn * 32 + p * 16 + b_colo;
                LDSM_X4T(bf[p], sb + (krow * BSTRIDEH + col) * 2);
            }
            #pragma unroll
            for (int mt = 0; mt < 4; mt++) {
                mma_f16(acc[mt][0], af[mt], &bf[0][0]);
                mma_f16(acc[mt][1], af[mt], &bf[0][2]);
                mma_f16(acc[mt][2], af[mt], &bf[1][0]);
                mma_f16(acc[mt][3], af[mt], &bf[1][2]);
            }
        }

        if (t + 2 < T)
            gemm_load_stage(A, W, N, K, bm, bn, (t + 2) * GBK, sbase + ((t + 2) % NSTG) * STGH * 2, tid);
        CP_COMMIT;
    }

    #pragma unroll
    for (int mt = 0; mt < 4; mt++) {
        int r0 = bm + wm * 64 + mt * 16 + grp;
        #pragma unroll
        for (int nt = 0; nt < 4; nt++) {
            int c0 = bn + wn * 32 + nt * 8 + 2 * tig;
            if (c0 >= N) continue;
            float v0 = acc[mt][nt][0], v1 = acc[mt][nt][1];
            float v2 = acc[mt][nt][2], v3 = acc[mt][nt][3];
            if (bias) {
                float b0 = bias[c0], b1 = bias[c0 + 1];
                v0 += b0; v1 += b1; v2 += b0; v3 += b1;
            }
            if (gate) {
                __half2 ga = *(const __half2*)&gate[(size_t)r0 * N + c0];
                __half2 gb = *(const __half2*)&gate[(size_t)(r0 + 8) * N + c0];
                v0 *= __low2float(ga); v1 *= __high2float(ga);
                v2 *= __low2float(gb); v3 *= __high2float(gb);
            }
            if (res) {
                float2 ra = *(const float2*)&res[(size_t)r0 * N + c0];
                float2 rb = *(const float2*)&res[(size_t)(r0 + 8) * N + c0];
                v0 += ra.x; v1 += ra.y; v2 += rb.x; v3 += rb.y;
            }
            if (outmode == 3) {
                v0 *= 1.0f / (1.0f + __expf(-v0));
                v1 *= 1.0f / (1.0f + __expf(-v1));
                v2 *= 1.0f / (1.0f + __expf(-v2));
                v3 *= 1.0f / (1.0f + __expf(-v3));
            }
            if (outmode >= 2) {
                __half* Ch = (__half*)C;
                *(__half2*)&Ch[(size_t)r0 * N + c0]       = __floats2half2_rn(v0, v1);
                *(__half2*)&Ch[(size_t)(r0 + 8) * N + c0] = __floats2half2_rn(v2, v3);
            } else {
                float* Cf = (float*)C;
                *(float2*)&Cf[(size_t)r0 * N + c0]       = make_float2(v0, v1);
                *(float2*)&Cf[(size_t)(r0 + 8) * N + c0] = make_float2(v2, v3);
            }
        }
    }
}

// ---------------- flash attention (fp16 mma, online softmax) ----------------
#define ASH 72
#define ATT_SMEM_BYTES ((64*ASH*2 + 128*ASH) * 2)

__global__ __launch_bounds__(256) void attn_kernel(
    const __half* __restrict__ qkv, __half* __restrict__ out)
{
    extern __shared__ __half smh[];
    __half* sK  = smh;
    __half* sV  = smh + 64 * ASH;
    __half* sQP = smh + 128 * ASH;
    const uint32_t sKu  = (uint32_t)__cvta_generic_to_shared(sK);
    const uint32_t sVu  = (uint32_t)__cvta_generic_to_shared(sV);
    const uint32_t sQPu = (uint32_t)__cvta_generic_to_shared(sQP);

    const int tid  = threadIdx.x;
    const int lane = tid & 31;
    const int warp = tid >> 5;
    const int grp  = lane >> 2;
    const int tig  = lane & 3;
    const int a_row  = lane & 15;
    const int a_koff = (lane >> 4) * 8;
    const int l15    = lane & 15;

    const int qb = gridDim.x - 1 - blockIdx.x;    // LPT
    const int q0 = qb * 128;
    const int h  = blockIdx.y;
    const int b  = blockIdx.z;

    const float slope = -exp2f(-0.5f * (float)(h + 1));
    const __half2 hscale = __float2half2_rn(0.125f);

    const __half* qbase = qkv + (size_t)(b * SS + q0) * LDQKV + h * HDIM;
    #pragma unroll
    for (int it = 0; it < 4; it++) {
        int idx = it * 256 + tid;
        int r = idx >> 3, c8 = (idx & 7) * 8;
        uint4 raw = *(const uint4*)&qbase[(size_t)r * LDQKV + c8];
        __half2* p = (__half2*)&raw;
        p[0] = __hmul2(p[0], hscale); p[1] = __hmul2(p[1], hscale);
        p[2] = __hmul2(p[2], hscale); p[3] = __hmul2(p[3], hscale);
        *(uint4*)&sQP[r * ASH + c8] = raw;
    }
    __syncthreads();

    uint32_t qf[4][4];
    #pragma unroll
    for (int ks = 0; ks < 4; ks++)
        LDSM_X4(qf[ks], sQPu + ((warp * 16 + a_row) * ASH + ks * 16 + a_koff) * 2);
    __syncthreads();

    const int myr = warp * 16 + grp;
    const int row0 = q0 + warp * 16 + grp;
    const int row1 = row0 + 8;
    const int warp_max_row = q0 + warp * 16 + 15;

    float m0 = -INFINITY, m1 = -INFINITY, l0 = 0.f, l1 = 0.f;
    float oacc[8][4];
    #pragma unroll
    for (int nt = 0; nt < 8; nt++)
        #pragma unroll
        for (int r = 0; r < 4; r++) oacc[nt][r] = 0.f;

    const int nkt = (q0 >> 6) + 2;
    const __half* kbase0 = qkv + (size_t)(b * SS) * LDQKV + DD     + h * HDIM;
    const __half* vbase0 = qkv + (size_t)(b * SS) * LDQKV + 2 * DD + h * HDIM;

    for (int kt = 0; kt < nkt; kt++) {
        const int j0 = kt * 64;
        const __half* kb_ = kbase0 + (size_t)j0 * LDQKV;
        const __half* vb_ = vbase0 + (size_t)j0 * LDQKV;
        #pragma unroll
        for (int it = 0; it < 2; it++) {
            int idx = it * 256 + tid;
            int r = idx >> 3, c8 = (idx & 7) * 8;
            *(uint4*)&sK[r * ASH + c8] = *(const uint4*)&kb_[(size_t)r * LDQKV + c8];
            *(uint4*)&sV[r * ASH + c8] = *(const uint4*)&vb_[(size_t)r * LDQKV + c8];
        }
        __syncthreads();

        if (j0 <= warp_max_row) {
            float sacc[8][4];
            #pragma unroll
            for (int nt = 0; nt < 8; nt++)
                #pragma unroll
                for (int r = 0; r < 4; r++) sacc[nt][r] = 0.f;

            #pragma unroll
            for (int ks = 0; ks < 4; ks++) {
                #pragma unroll
                for (int nt = 0; nt < 8; nt++) {
                    uint32_t kf[2];
                    LDSM_X2(kf, sKu + ((nt * 8 + (l15 & 7)) * ASH + ks * 16 + (l15 >> 3) * 8) * 2);
                    mma_f16(sacc[nt], qf[ks], kf);
                }
            }

            float mn0 = m0, mn1 = m1;
            #pragma unroll
            for (int nt = 0; nt < 8; nt++) {
                int cbase = j0 + nt * 8 + 2 * tig;
                #pragma unroll
                for (int r = 0; r < 4; r++) {
                    int col = cbase + (r & 1);
                    int rw = (r < 2) ? row0 : row1;
                    float s;
                    if (col > rw) s = -INFINITY;
                    else          s = sacc[nt][r] + slope * (float)(rw - col);
                    sacc[nt][r] = s;
                    if (r < 2) mn0 = fmaxf(mn0, s); else mn1 = fmaxf(mn1, s);
                }
            }
            mn0 = fmaxf(mn0, __shfl_xor_sync(FULLMASK, mn0, 1));
            mn0 = fmaxf(mn0, __shfl_xor_sync(FULLMASK, mn0, 2));
            mn1 = fmaxf(mn1, __shfl_xor_sync(FULLMASK, mn1, 1));
            mn1 = fmaxf(mn1, __shfl_xor_sync(FULLMASK, mn1, 2));

            float f0 = __expf(m0 - mn0);
            float f1 = __expf(m1 - mn1);
            m0 = mn0; m1 = mn1;

            float rs0 = 0.f, rs1 = 0.f;
            #pragma unroll
            for (int nt = 0; nt < 8; nt++) {
                float p0 = __expf(sacc[nt][0] - m0);
                float p1 = __expf(sacc[nt][1] - m0);
                float p2 = __expf(sacc[nt][2] - m1);
                float p3 = __expf(sacc[nt][3] - m1);
                sacc[nt][0] = p0; sacc[nt][1] = p1; sacc[nt][2] = p2; sacc[nt][3] = p3;
                rs0 += p0 + p1; rs1 += p2 + p3;
            }
            rs0 += __shfl_xor_sync(FULLMASK, rs0, 1);
            rs0 += __shfl_xor_sync(FULLMASK, rs0, 2);
            rs1 += __shfl_xor_sync(FULLMASK, rs1, 1);
            rs1 += __shfl_xor_sync(FULLMASK, rs1, 2);
            l0 = l0 * f0 + rs0;
            l1 = l1 * f1 + rs1;

            #pragma unroll
            for (int nt = 0; nt < 8; nt++) {
                oacc[nt][0] *= f0; oacc[nt][1] *= f0;
                oacc[nt][2] *= f1; oacc[nt][3] *= f1;
            }

            #pragma unroll
            for (int nt = 0; nt < 8; nt++) {
                *(__half2*)&sQP[(myr    ) * ASH + nt * 8 + 2 * tig] = __floats2half2_rn(sacc[nt][0], sacc[nt][1]);
                *(__half2*)&sQP[(myr + 8) * ASH + nt * 8 + 2 * tig] = __floats2half2_rn(sacc[nt][2], sacc[nt][3]);
            }
            __syncwarp();

            #pragma unroll
            for (int ks = 0; ks < 4; ks++) {
                uint32_t pf[4];
                LDSM_X4(pf, sQPu + ((warp * 16 + a_row) * ASH + ks * 16 + a_koff) * 2);
                #pragma unroll
                for (int nt = 0; nt < 8; nt++) {
                    uint32_t vf[2];
                    LDSM_X2T(vf, sVu + ((ks * 16 + l15) * ASH + nt * 8) * 2);
                    mma_f16(oacc[nt], pf, vf);
                }
            }
        }
        __syncthreads();
    }

    float inv0 = 1.0f / l0, inv1 = 1.0f / l1;
    __half* obase = out + (size_t)(b * SS) * DD + h * HDIM;
    #pragma unroll
    for (int nt = 0; nt < 8; nt++) {
        int d = nt * 8 + 2 * tig;
        *(__half2*)&obase[(size_t)row0 * DD + d] =
            __floats2half2_rn(oacc[nt][0] * inv0, oacc[nt][1] * inv0);
        *(__half2*)&obase[(size_t)row1 * DD + d] =
            __floats2half2_rn(oacc[nt][2] * inv1, oacc[nt][3] * inv1);
    }
}

// ---------------- launch ----------------
extern "C" void kernel_launch(void* const* d_in, const int* in_sizes, int n_in,
                              void* d_out, int out_size)
{
    const float* x      = (const float*)d_in[0];
    const float* wq     = (const float*)d_in[1];
    const float* bq     = (const float*)d_in[2];
    const float* wk     = (const float*)d_in[3];
    const float* bk     = (const float*)d_in[4];
    const float* wv     = (const float*)d_in[5];
    const float* bv     = (const float*)d_in[6];
    const float* wo     = (const float*)d_in[7];
    const float* bo     = (const float*)d_in[8];
    const float* w_gate = (const float*)d_in[9];
    const float* w_up   = (const float*)d_in[10];
    const float* w_down = (const float*)d_in[11];
    const float* ln1w   = (const float*)d_in[12];
    const float* ln2w   = (const float*)d_in[13];
    float* out = (float*)d_out;

    static __half *pH = nullptr, *pQKV, *pAtt, *pH2, *pSG, *pAct, *pCW;
    static float *pRes1, *pBcat;
    if (!pH) {
        cudaGetSymbolAddress((void**)&pH,    g_h);
        cudaGetSymbolAddress((void**)&pQKV,  g_qkv);
        cudaGetSymbolAddress((void**)&pAtt,  g_att);
        cudaGetSymbolAddress((void**)&pRes1, g_res1);
        cudaGetSymbolAddress((void**)&pH2,   g_h2);
        cudaGetSymbolAddress((void**)&pSG,   g_sgate);
        cudaGetSymbolAddress((void**)&pAct,  g_act);
        cudaGetSymbolAddress((void**)&pCW,   g_cw);
        cudaGetSymbolAddress((void**)&pBcat, g_bcat);
        cudaFuncSetAttribute(attn_kernel, cudaFuncAttributeMaxDynamicSharedMemorySize, ATT_SMEM_BYTES);
        cudaFuncSetAttribute(gemm_f16_kernel, cudaFuncAttributeMaxDynamicSharedMemorySize, GEMM_SMEM_BYTES);
    }

    // 0. weight prep
    const int nDD4 = DD * DD / 4, nDI4 = DD * II / 4;
    cvt_qkv_kernel<<<3 * nDD4 / 256, 256>>>(wq, wk, wv, pCW + CW_QKV);
    bcat_kernel<<<(LDQKV + 255) / 256, 256>>>(bq, bk, bv, pBcat);
    cvt_all_kernel<<<(nDD4 + 3 * nDI4 + 255) / 256, 256>>>(wo, w_gate, w_up, w_down, pCW);

    dim3 blk(256);

    // 1. h = rmsnorm(x) (fp16)
    rmsnorm_kernel<<<MROWS, 256>>>(x, ln1w, pH);

    // 2. fused QKV projection (out fp16)
    dim3 gQKV(LDQKV / GBN, MROWS / GBM);
    gemm_f16_kernel<<<gQKV, blk, GEMM_SMEM_BYTES>>>(pH, pCW + CW_QKV, pBcat, nullptr, nullptr, pQKV, MROWS, LDQKV, DD, 2);

    // 3. flash attention (fp16 mma)
    dim3 ga(SS / 128, HH, BB);
    attn_kernel<<<ga, 256, ATT_SMEM_BYTES>>>(pQKV, pAtt);

    // 4. res1 = att @ wo + bo + x (fp32)
    dim3 gD(DD / GBN, MROWS / GBM);
    gemm_f16_kernel<<<gD, blk, GEMM_SMEM_BYTES>>>(pAtt, pCW + CW_O, bo, x, nullptr, pRes1, MROWS, DD, DD, 0);

    // 5. h2 = rmsnorm(res1) (fp16)
    rmsnorm_kernel<<<MROWS, 256>>>(pRes1, ln2w, pH2);

    // 6. sgate = silu(h2 @ w_gate) (fp16)
    dim3 gI((II + GBN - 1) / GBN, MROWS / GBM);
    gemm_f16_kernel<<<gI, blk, GEMM_SMEM_BYTES>>>(pH2, pCW + CW_G, nullptr, nullptr, nullptr, pSG, MROWS, II, DD, 3);

    // 7. act = sgate * (h2 @ w_up) (fp16)
    gemm_f16_kernel<<<gI, blk, GEMM_SMEM_BYTES>>>(pH2, pCW + CW_U, nullptr, nullptr, pSG, pAct, MROWS, II, DD, 2);

    // 8. out = act @ w_down + res1 (fp32)
    gemm_f16_kernel<<<gD, blk, GEMM_SMEM_BYTES>>>(pAct, pCW + CW_D, nullptr, pRes1, nullptr, out, MROWS, DD, II, 0);
}